// round 3
// baseline (speedup 1.0000x reference)
#include <cuda_runtime.h>
#include <cuda_bf16.h>

#define N_NODES 50000
#define N_EDGES 800000
#define D 128

typedef unsigned long long u64;

// ---------------------------------------------------------------------------
// Scratch (__device__ globals per allocation-free rule)
// ---------------------------------------------------------------------------
__device__ __align__(16) float g_agg[N_NODES * D];   // normalized mean agg
__device__ int g_cnt[N_NODES];        // in-degree (histogram)
__device__ int g_off[N_NODES];        // CSR row offsets (exclusive prefix)
__device__ int g_cur[N_NODES];        // fill cursors
__device__ int g_csr[N_EDGES];        // src node per CSR slot

// ---------------------------------------------------------------------------
// K1: zero the degree histogram (only array needing re-zero per replay)
// ---------------------------------------------------------------------------
__global__ void zero_cnt() {
    int i = blockIdx.x * blockDim.x + threadIdx.x;
    if (i < N_NODES) g_cnt[i] = 0;
}

// ---------------------------------------------------------------------------
// K2: degree histogram over destinations
// ---------------------------------------------------------------------------
__global__ void __launch_bounds__(256) hist_kernel(const int* __restrict__ ei) {
    int e = blockIdx.x * blockDim.x + threadIdx.x;
    if (e >= N_EDGES) return;
    int dst = ei[N_EDGES + e];
    if ((unsigned)dst < N_NODES) atomicAdd(&g_cnt[dst], 1);
}

// ---------------------------------------------------------------------------
// K3: single-block exclusive scan -> g_off, g_cur
// 1024 threads, chunk of 49 nodes each; Kogge-Stone over block partials.
// ---------------------------------------------------------------------------
__global__ void __launch_bounds__(1024) scan_kernel() {
    __shared__ int part[1024];
    const int t = threadIdx.x;
    const int CH = (N_NODES + 1023) / 1024;      // 49
    int beg = t * CH;
    int end = beg + CH; if (end > N_NODES) end = N_NODES;
    int s = 0;
    for (int i = beg; i < end; i++) s += g_cnt[i];
    part[t] = s;
    __syncthreads();
    #pragma unroll
    for (int off = 1; off < 1024; off <<= 1) {
        int tmp = 0;
        if (t >= off) tmp = part[t - off];
        __syncthreads();
        if (t >= off) part[t] += tmp;
        __syncthreads();
    }
    int run = part[t] - s;                        // exclusive prefix at chunk start
    for (int i = beg; i < end; i++) {
        g_off[i] = run;
        g_cur[i] = run;
        run += g_cnt[i];
    }
}

// ---------------------------------------------------------------------------
// K4: bucket fill — scatter src ids into CSR slots
// ---------------------------------------------------------------------------
__global__ void __launch_bounds__(256) fill_kernel(const int* __restrict__ ei) {
    int e = blockIdx.x * blockDim.x + threadIdx.x;
    if (e >= N_EDGES) return;
    int src = ei[e];
    int dst = ei[N_EDGES + e];
    if ((unsigned)src >= N_NODES || (unsigned)dst >= N_NODES) return;
    int pos = atomicAdd(&g_cur[dst], 1);
    g_csr[pos] = src;
}

// ---------------------------------------------------------------------------
// K5: gather-aggregate. One warp per node; lane owns float4 of the row.
// Writes normalized mean directly (no atomics, single agg write).
// ---------------------------------------------------------------------------
__global__ void __launch_bounds__(256) gather_kernel(const float* __restrict__ x) {
    unsigned tid = blockIdx.x * blockDim.x + threadIdx.x;
    unsigned n = tid >> 5;
    unsigned lane = tid & 31;
    if (n >= N_NODES) return;

    int beg = g_off[n];
    int deg = g_cnt[n];
    int end = beg + deg;

    float4 acc = make_float4(0.f, 0.f, 0.f, 0.f);
    int j = beg;
    int src_next = (j < end) ? g_csr[j] : 0;
    while (j < end) {
        int src = src_next;
        ++j;
        src_next = (j < end) ? g_csr[j] : 0;       // prefetch next index
        float4 v = *(const float4*)(x + (size_t)src * D + lane * 4);
        acc.x += v.x; acc.y += v.y; acc.z += v.z; acc.w += v.w;
    }
    float inv = 1.0f / fmaxf((float)deg, 1.0f);
    acc.x *= inv; acc.y *= inv; acc.z *= inv; acc.w *= inv;
    *(float4*)(g_agg + (size_t)n * D + lane * 4) = acc;
}

// ---------------------------------------------------------------------------
// K6: fused  out = relu( agg @ W_l^T + b_l + x @ W_r^T )
// agg already normalized. Inner product over k=0..255 (concat of agg|x).
// Packed fp32x2 FMA (sm_103a) to halve FMA-pipe pressure.
// ---------------------------------------------------------------------------
#define TN 64
#define WSTR 132
#define SMEM_FLOATS (256 * WSTR + TN * 256)
#define SMEM_BYTES  (SMEM_FLOATS * 4)

__device__ __forceinline__ void ffma2(u64& d, u64 a, u64 b) {
    asm("fma.rn.f32x2 %0, %1, %2, %0;" : "+l"(d) : "l"(a), "l"(b));
}

__global__ void __launch_bounds__(256, 1) sage_gemm(
    const float* __restrict__ x,
    const float* __restrict__ W_l,
    const float* __restrict__ b_l,
    const float* __restrict__ W_r,
    float* __restrict__ out)
{
    extern __shared__ float sm[];
    float* Wsm  = sm;                    // 256 x WSTR (k-major, cols contiguous)
    float* insm = sm + 256 * WSTR;       // TN x 256

    const int t = threadIdx.x;
    const int nodeBase = blockIdx.x * TN;

    // W_l / W_r transposed into Wsm: Wsm[k][c] = W[c][k]
    #pragma unroll 4
    for (int l = t; l < D * D; l += 256) {
        int c = l >> 7;
        int k = l & 127;
        Wsm[k * WSTR + c]         = W_l[l];
        Wsm[(k + 128) * WSTR + c] = W_r[l];
    }

    // Input tile: insm[node][k] = (k<128 ? agg[n][k] : x[n][k-128])
    for (int l = t; l < TN * 256; l += 256) {
        int node = l >> 8;
        int k = l & 255;
        int n = nodeBase + node;
        float v = 0.0f;
        if (n < N_NODES) {
            if (k < 128) v = g_agg[(size_t)n * D + k];
            else         v = x[(size_t)n * D + (k - 128)];
        }
        insm[l] = v;
    }
    __syncthreads();

    const int c0 = (t & 31) * 4;   // output column group (lane)
    const int n0 = (t >> 5) * 8;   // node group (warp)

    u64 acc2[8][2];
    #pragma unroll
    for (int i = 0; i < 8; i++) { acc2[i][0] = 0ull; acc2[i][1] = 0ull; }

    #pragma unroll 2
    for (int k = 0; k < 256; k++) {
        float4 w = *(const float4*)&Wsm[k * WSTR + c0];
        u64 wlo, whi;
        asm("mov.b64 %0, {%1, %2};" : "=l"(wlo) : "f"(w.x), "f"(w.y));
        asm("mov.b64 %0, {%1, %2};" : "=l"(whi) : "f"(w.z), "f"(w.w));
        #pragma unroll
        for (int i = 0; i < 8; i++) {
            float a = insm[(n0 + i) * 256 + k];
            u64 aa;
            asm("mov.b64 %0, {%1, %1};" : "=l"(aa) : "f"(a));
            ffma2(acc2[i][0], aa, wlo);
            ffma2(acc2[i][1], aa, whi);
        }
    }

    float4 bias = *(const float4*)&b_l[c0];
    #pragma unroll
    for (int i = 0; i < 8; i++) {
        int n = nodeBase + n0 + i;
        if (n < N_NODES) {
            float a0, a1, a2, a3;
            asm("mov.b64 {%0, %1}, %2;" : "=f"(a0), "=f"(a1) : "l"(acc2[i][0]));
            asm("mov.b64 {%0, %1}, %2;" : "=f"(a2), "=f"(a3) : "l"(acc2[i][1]));
            float4 o;
            o.x = fmaxf(a0 + bias.x, 0.f);
            o.y = fmaxf(a1 + bias.y, 0.f);
            o.z = fmaxf(a2 + bias.z, 0.f);
            o.w = fmaxf(a3 + bias.w, 0.f);
            *(float4*)&out[(size_t)n * D + c0] = o;
        }
    }
}

// ---------------------------------------------------------------------------
extern "C" void kernel_launch(void* const* d_in, const int* in_sizes, int n_in,
                              void* d_out, int out_size) {
    const float* x   = (const float*)d_in[0];
    const int*   ei  = (const int*)d_in[1];
    const float* W_l = (const float*)d_in[2];
    const float* b_l = (const float*)d_in[3];
    const float* W_r = (const float*)d_in[4];
    float*       out = (float*)d_out;

    cudaFuncSetAttribute(sage_gemm,
                         cudaFuncAttributeMaxDynamicSharedMemorySize,
                         SMEM_BYTES);

    zero_cnt<<<(N_NODES + 255) / 256, 256>>>();
    hist_kernel<<<(N_EDGES + 255) / 256, 256>>>(ei);
    scan_kernel<<<1, 1024>>>();
    fill_kernel<<<(N_EDGES + 255) / 256, 256>>>(ei);
    gather_kernel<<<(N_NODES * 32 + 255) / 256, 256>>>(x);
    sage_gemm<<<(N_NODES + TN - 1) / TN, 256, SMEM_BYTES>>>(x, W_l, b_l, W_r, out);
}